// round 16
// baseline (speedup 1.0000x reference)
#include <cuda_runtime.h>
#include <cuda_bf16.h>
#include <mma.h>
#include <stdint.h>
#include <math.h>

using namespace nvcuda;

#define INF_DIM 128
#define HDIM    64
#define HEADS   4
#define DDIM    16
#define EDIM    16
#define MAXN    50176
#define MAXE    800512
#define BUCKET  128

// ---------------- static device scratch ----------------
__device__ float g_q [MAXN * HDIM];
__device__ float g_kv[MAXN * 2 * HDIM];          // per node: [ k[64f] | v[64f] ]
__device__ float g_s [MAXN * HDIM];
__device__ float g_r [MAXN * HEADS];
__device__ float g_wbar[HDIM];
__device__ int   g_cnt[MAXN];
__device__ int2  g_bkt[(size_t)MAXN * BUCKET];
__device__ int   g_flag;                         // 1 iff edge_attr all-ones
__device__ int   g_gemm_ok;                      // 1 iff tensor GEMM verified
__device__ __nv_bfloat16 g_xh[(size_t)MAXN * 128];
__device__ __nv_bfloat16 g_xl[(size_t)MAXN * 128];
__device__ __nv_bfloat16 g_wh[256 * 128];        // B-order: [out col 0..255][k]
__device__ __nv_bfloat16 g_wl[256 * 128];

// ---------------- f32x2 helpers (fallback gemm) ----------------
__device__ __forceinline__ unsigned long long pack2(float lo, float hi) {
    unsigned long long r;
    asm("mov.b64 %0, {%1, %2};" : "=l"(r) : "f"(lo), "f"(hi));
    return r;
}
__device__ __forceinline__ void fma2(unsigned long long& d, unsigned long long a, unsigned long long b) {
    asm("fma.rn.f32x2 %0, %1, %2, %0;" : "+l"(d) : "l"(a), "l"(b));
}
__device__ __forceinline__ void unpack2(unsigned long long v, float& lo, float& hi) {
    asm("mov.b64 {%0, %1}, %2;" : "=f"(lo), "=f"(hi) : "l"(v));
}

// ---------------- K1: zero counts + flags + wbar ----------------
__global__ void zero_all_kernel(const float* __restrict__ We, int n) {
    int i = blockIdx.x * blockDim.x + threadIdx.x;
    if (i < n) g_cnt[i] = 0;
    if (i == 0) { g_flag = 1; g_gemm_ok = 1; }
    if (blockIdx.x == 0 && threadIdx.x < HDIM) {
        float s = 0.f;
#pragma unroll
        for (int r = 0; r < EDIM; r++) s += We[r * HDIM + threadIdx.x];
        g_wbar[threadIdx.x] = s;
    }
}

// ---------------- K2: split W into bf16 hi/lo, B-order [n][k] ----------------
__global__ void split_w_kernel(
    const float* __restrict__ Wq, const float* __restrict__ Wk,
    const float* __restrict__ Wv, const float* __restrict__ Ws)
{
    int idx = blockIdx.x * 256 + threadIdx.x;     // 32768 elements
    int nn = idx >> 7, k = idx & 127;
    int m = nn >> 6, col = nn & 63;
    const float* W = (m == 0) ? Wq : (m == 1) ? Wk : (m == 2) ? Wv : Ws;
    float w = W[k * HDIM + col];
    __nv_bfloat16 hi = __float2bfloat16(w);
    __nv_bfloat16 lo = __float2bfloat16(w - __bfloat162float(hi));
    g_wh[idx] = hi;
    g_wl[idx] = lo;
}

// ---------------- K3: FAT = split x into bf16 hi/lo (blocks [0,Gx)) + edge scatter ----
__global__ void __launch_bounds__(256) splitx_scatter_kernel(
    const float* __restrict__ x, const int* __restrict__ ei,
    const float* __restrict__ ea, int total4, int E, int Gx)
{
    if (blockIdx.x >= Gx) {
        int e = (blockIdx.x - Gx) * 256 + threadIdx.x;
        if (e < E) {
            int d = ei[E + e];
            int pos = atomicAdd(&g_cnt[d], 1);
            g_bkt[(size_t)d * BUCKET + pos] = make_int2(e, ei[e]);
            const float4* af = (const float4*)(ea + (size_t)e * EDIM);
            float4 a0 = af[0], a1 = af[1], a2 = af[2], a3 = af[3];
            bool ones = a0.x == 1.f && a0.y == 1.f && a0.z == 1.f && a0.w == 1.f
                     && a1.x == 1.f && a1.y == 1.f && a1.z == 1.f && a1.w == 1.f
                     && a2.x == 1.f && a2.y == 1.f && a2.z == 1.f && a2.w == 1.f
                     && a3.x == 1.f && a3.y == 1.f && a3.z == 1.f && a3.w == 1.f;
            if (!ones) g_flag = 0;
        }
        return;
    }
    int i4 = blockIdx.x * 256 + threadIdx.x;
    if (i4 >= total4) return;
    float4 v = ((const float4*)x)[i4];
    __nv_bfloat16 h0 = __float2bfloat16(v.x), h1 = __float2bfloat16(v.y);
    __nv_bfloat16 h2 = __float2bfloat16(v.z), h3 = __float2bfloat16(v.w);
    __nv_bfloat162* ph = (__nv_bfloat162*)g_xh;
    __nv_bfloat162* pl = (__nv_bfloat162*)g_xl;
    ph[i4 * 2 + 0] = __nv_bfloat162(h0, h1);
    ph[i4 * 2 + 1] = __nv_bfloat162(h2, h3);
    pl[i4 * 2 + 0] = __nv_bfloat162(__float2bfloat16(v.x - __bfloat162float(h0)),
                                    __float2bfloat16(v.y - __bfloat162float(h1)));
    pl[i4 * 2 + 1] = __nv_bfloat162(__float2bfloat16(v.z - __bfloat162float(h2)),
                                    __float2bfloat16(v.w - __bfloat162float(h3)));
}

// ---------------- K4: WMMA bf16x3 GEMM: 32 nodes x 256 cols per CTA ----------------
// warp (mt = w&1, ng = w>>2? no: ng = w>>1) -> 16-node x 64-col tile (4 accums).
// D = Xh@Wh + Xh@Wl + Xl@Wh, fp32 accum. B staged in smem (hi+lo 128KB), A from global.
__global__ void __launch_bounds__(256) mma_kernel(
    const float* __restrict__ bq, const float* __restrict__ bk,
    const float* __restrict__ bv, const float* __restrict__ bs, int n)
{
    extern __shared__ char smem[];
    __nv_bfloat16* sBh = (__nv_bfloat16*)smem;            // 65536 B
    __nv_bfloat16* sBl = sBh + 256 * 128;                 // 65536 B
    float* sC    = (float*)(sBl + 256 * 128);             // 32768 B
    float* sbias = sC + 32 * 256;                         // 1024 B

    int tid = threadIdx.x;
    int wid = tid >> 5;
    int nb = blockIdx.x * 32;

    // stage B hi/lo (4096 uint4 each) + biases
    {
        const uint4* wh4 = (const uint4*)g_wh;
        const uint4* wl4 = (const uint4*)g_wl;
        uint4* dh = (uint4*)sBh;
        uint4* dl = (uint4*)sBl;
        for (int i = tid; i < 4096; i += 256) { dh[i] = wh4[i]; dl[i] = wl4[i]; }
        for (int i = tid; i < 256; i += 256) {
            float b;
            if (i < 64) b = bq[i];
            else if (i < 128) b = bk[i - 64];
            else if (i < 192) b = bv[i - 128];
            else b = bs[i - 192];
            sbias[i] = b;
        }
    }
    __syncthreads();

    int mt = wid & 1;          // M-tile (16 nodes)
    int ng = wid >> 1;         // 64-col group
    const __nv_bfloat16* Ah = g_xh + (size_t)(nb + mt * 16) * 128;
    const __nv_bfloat16* Al = g_xl + (size_t)(nb + mt * 16) * 128;

    wmma::fragment<wmma::accumulator, 16, 16, 16, float> acc[4];
#pragma unroll
    for (int s = 0; s < 4; s++) wmma::fill_fragment(acc[s], 0.0f);

    for (int ks = 0; ks < 8; ks++) {
        wmma::fragment<wmma::matrix_a, 16, 16, 16, __nv_bfloat16, wmma::row_major> ah, al;
        wmma::load_matrix_sync(ah, Ah + ks * 16, 128);
        wmma::load_matrix_sync(al, Al + ks * 16, 128);
#pragma unroll
        for (int sub = 0; sub < 4; sub++) {
            wmma::fragment<wmma::matrix_b, 16, 16, 16, __nv_bfloat16, wmma::col_major> bh, bl;
            int ncol = ng * 64 + sub * 16;
            wmma::load_matrix_sync(bh, sBh + ncol * 128 + ks * 16, 128);
            wmma::load_matrix_sync(bl, sBl + ncol * 128 + ks * 16, 128);
            wmma::mma_sync(acc[sub], ah, bh, acc[sub]);
            wmma::mma_sync(acc[sub], ah, bl, acc[sub]);
            wmma::mma_sync(acc[sub], al, bh, acc[sub]);
        }
    }

#pragma unroll
    for (int sub = 0; sub < 4; sub++)
        wmma::store_matrix_sync(sC + (mt * 16) * 256 + ng * 64 + sub * 16,
                                acc[sub], 256, wmma::mem_row_major);
    __syncthreads();

    // write-out with bias + scale: 2048 float4s
    for (int i = tid; i < 2048; i += 256) {
        int row = i >> 6;
        int c = (i & 63) * 4;
        int node = nb + row;
        if (node >= n) continue;
        const float4 v = *(const float4*)(sC + row * 256 + c);
        const float4 bi = *(const float4*)(sbias + c);
        int region = c >> 6;
        float scl = (region == 0) ? 0.25f : 1.0f;
        float4 o;
        o.x = (v.x + bi.x) * scl;
        o.y = (v.y + bi.y) * scl;
        o.z = (v.z + bi.z) * scl;
        o.w = (v.w + bi.w) * scl;
        float* dst;
        if (region == 0)      dst = g_q  + (size_t)node * 64  + c;
        else if (region == 1) dst = g_kv + (size_t)node * 128 + (c - 64);
        else if (region == 2) dst = g_kv + (size_t)node * 128 + 64 + (c - 128);
        else                  dst = g_s  + (size_t)node * 64  + (c - 192);
        *(float4*)dst = o;
    }
}

// ---------------- K5: verify tensor GEMM on 128 samples ----------------
__global__ void check_kernel(
    const float* __restrict__ x,
    const float* __restrict__ Wq, const float* __restrict__ bq,
    const float* __restrict__ Wk, const float* __restrict__ bk,
    const float* __restrict__ Wv, const float* __restrict__ bv,
    const float* __restrict__ Ws, const float* __restrict__ bs, int n)
{
    int t = threadIdx.x;
    int node = (t * 397 + 13) % n;
    int c = (t * 67 + 5) & 255;
    int m = c >> 6, col = c & 63;
    const float* W = (m == 0) ? Wq : (m == 1) ? Wk : (m == 2) ? Wv : Ws;
    const float* B = (m == 0) ? bq : (m == 1) ? bk : (m == 2) ? bv : bs;
    float acc = B[col];
    for (int k = 0; k < 128; k++) acc = fmaf(x[(size_t)node * 128 + k], W[k * HDIM + col], acc);
    float expv, got;
    if (m == 0)      { expv = acc * 0.25f; got = g_q[(size_t)node * 64 + col]; }
    else if (m == 1) { expv = acc; got = g_kv[(size_t)node * 128 + col]; }
    else if (m == 2) { expv = acc; got = g_kv[(size_t)node * 128 + 64 + col]; }
    else             { expv = acc; got = g_s[(size_t)node * 64 + col]; }
    float rel = fabsf(got - expv) / fmaxf(fabsf(expv), 1.0f);
    if (rel > 1e-2f) g_gemm_ok = 0;
}

// ---------------- K6: fallback FFMA2 GEMM (runs only if check failed) ----------------
__global__ void __launch_bounds__(128, 8) fallback_gemm_kernel(
    const float* __restrict__ x,
    const float* __restrict__ Wq, const float* __restrict__ bq,
    const float* __restrict__ Wk, const float* __restrict__ bk,
    const float* __restrict__ Wv, const float* __restrict__ bv,
    const float* __restrict__ Ws, const float* __restrict__ bs, int n)
{
    if (g_gemm_ok) return;

    __shared__ float4 xs_p[64 * 4];
    int nb = blockIdx.x * 8;
    int tid = threadIdx.x;

    for (int i = tid; i < 256; i += 128) {
        int kp = i >> 2, np = i & 3;
        int r0 = nb + 2 * np, r1 = r0 + 1;
        float2 a = make_float2(0.f, 0.f), b = make_float2(0.f, 0.f);
        if (r0 < n) a = *(const float2*)(x + (size_t)r0 * INF_DIM + 2 * kp);
        if (r1 < n) b = *(const float2*)(x + (size_t)r1 * INF_DIM + 2 * kp);
        xs_p[kp * 4 + np] = make_float4(a.x, b.x, a.y, b.y);
    }
    __syncthreads();

    int m = tid >> 5, cp = tid & 31;
    const float* W = (m == 0) ? Wq : (m == 1) ? Wk : (m == 2) ? Wv : Ws;
    const float* B = (m == 0) ? bq : (m == 1) ? bk : (m == 2) ? bv : bs;
    float scale = (m == 0) ? 0.25f : 1.0f;

    unsigned long long accE[4], accO[4];
#pragma unroll
    for (int i = 0; i < 4; i++) { accE[i] = 0ull; accO[i] = 0ull; }

    const ulonglong2* xsu = (const ulonglong2*)xs_p;
    for (int kp = 0; kp < 64; kp++) {
        float2 wA = *(const float2*)(W + (size_t)(2 * kp) * HDIM + 2 * cp);
        float2 wB = *(const float2*)(W + (size_t)(2 * kp + 1) * HDIM + 2 * cp);
        unsigned long long b0e = pack2(wA.x, wA.x);
        unsigned long long b0o = pack2(wA.y, wA.y);
        unsigned long long b1e = pack2(wB.x, wB.x);
        unsigned long long b1o = pack2(wB.y, wB.y);
#pragma unroll
        for (int np = 0; np < 4; np++) {
            ulonglong2 xv = xsu[kp * 4 + np];
            fma2(accE[np], xv.x, b0e);
            fma2(accE[np], xv.y, b1e);
            fma2(accO[np], xv.x, b0o);
            fma2(accO[np], xv.y, b1o);
        }
    }

    float2 bias = *(const float2*)(B + 2 * cp);
    int colE = 2 * cp;
#pragma unroll
    for (int np = 0; np < 4; np++) {
        float e0, e1, o0, o1;
        unpack2(accE[np], e0, e1);
        unpack2(accO[np], o0, o1);
        float2 r0v = make_float2((e0 + bias.x) * scale, (o0 + bias.y) * scale);
        float2 r1v = make_float2((e1 + bias.x) * scale, (o1 + bias.y) * scale);
        int n0 = nb + 2 * np, n1 = n0 + 1;
        if (m == 0) {
            if (n0 < n) *(float2*)(g_q + (size_t)n0 * HDIM + colE) = r0v;
            if (n1 < n) *(float2*)(g_q + (size_t)n1 * HDIM + colE) = r1v;
        } else if (m == 1) {
            if (n0 < n) *(float2*)(g_kv + (size_t)n0 * 128 + colE) = r0v;
            if (n1 < n) *(float2*)(g_kv + (size_t)n1 * 128 + colE) = r1v;
        } else if (m == 2) {
            if (n0 < n) *(float2*)(g_kv + (size_t)n0 * 128 + 64 + colE) = r0v;
            if (n1 < n) *(float2*)(g_kv + (size_t)n1 * 128 + 64 + colE) = r1v;
        } else {
            if (n0 < n) *(float2*)(g_s + (size_t)n0 * HDIM + colE) = r0v;
            if (n1 < n) *(float2*)(g_s + (size_t)n1 * HDIM + colE) = r1v;
        }
    }
}

// ---------------- K7a: attention specialized for edge_attr == ones ----------------
template <bool WRITE_ALPHA>
__global__ void __launch_bounds__(256, 5) attn_ones_kernel(
    float* __restrict__ out, float* __restrict__ exbuf, int n)
{
    if (!g_flag) return;

    __shared__ float wbar[HDIM];
    if (threadIdx.x < HDIM) wbar[threadIdx.x] = g_wbar[threadIdx.x];
    __syncthreads();

    int wid = threadIdx.x >> 5, lane = threadIdx.x & 31;
    int node = blockIdx.x * 8 + wid;
    if (node >= n) return;

    int half = lane >> 4;
    int h = (lane & 15) >> 2;
    int j = lane & 3;
    int hb = h * DDIM;
    int kidx = lane & 15;
    int vidx = 16 + (lane & 15);

    float q0, q1, q2, q3, cst;
    {
        const float4* Q = (const float4*)(g_q + (size_t)node * HDIM + hb);
        float4 qa = Q[0], qb = Q[1], qc = Q[2], qd = Q[3];
        float4 qf = (j == 0) ? qa : (j == 1) ? qb : (j == 2) ? qc : qd;
        q0 = qf.x; q1 = qf.y; q2 = qf.z; q3 = qf.w;
        const float4* wb = (const float4*)(wbar + hb);
        float4 w0 = wb[0], w1 = wb[1], w2 = wb[2], w3 = wb[3];
        float s = 0.f;
        s = fmaf(qa.x, w0.x, s); s = fmaf(qa.y, w0.y, s); s = fmaf(qa.z, w0.z, s); s = fmaf(qa.w, w0.w, s);
        s = fmaf(qb.x, w1.x, s); s = fmaf(qb.y, w1.y, s); s = fmaf(qb.z, w1.z, s); s = fmaf(qb.w, w1.w, s);
        s = fmaf(qc.x, w2.x, s); s = fmaf(qc.y, w2.y, s); s = fmaf(qc.z, w2.z, s); s = fmaf(qc.w, w2.w, s);
        s = fmaf(qd.x, w3.x, s); s = fmaf(qd.y, w3.y, s); s = fmaf(qd.z, w3.z, s); s = fmaf(qd.w, w3.w, s);
        cst = s;
    }

    const int2* bp = g_bkt + (size_t)node * BUCKET;
    int cnt = g_cnt[node];

    float av0 = 0.f, av1 = 0.f, av2 = 0.f, av3 = 0.f;
    float ssum = 0.f;
    const float4* kv4 = (const float4*)g_kv;

    int i = 0;
    int4 eP = make_int4(0, 0, 0, 0), eQ = make_int4(0, 0, 0, 0);
    if (cnt >= 4) {
        eP = *(const int4*)(bp);
        eQ = *(const int4*)(bp + 2);
    }
    while (i + 4 <= cnt) {
        int eidA = half ? eP.z : eP.x;  int srcA = half ? eP.w : eP.y;
        int eidB = half ? eQ.z : eQ.x;  int srcB = half ? eQ.w : eQ.y;

        float4 kA = kv4[(size_t)srcA * 32 + kidx];
        float4 vA = kv4[(size_t)srcA * 32 + vidx];
        float4 kB = kv4[(size_t)srcB * 32 + kidx];
        float4 vB = kv4[(size_t)srcB * 32 + vidx];

        int ni = i + 4;
        if (ni + 4 <= cnt) {
            eP = *(const int4*)(bp + ni);
            eQ = *(const int4*)(bp + ni + 2);
        }
        i = ni;

        float pA = kA.x * q0 + kA.y * q1 + kA.z * q2 + kA.w * q3;
        float pB = kB.x * q0 + kB.y * q1 + kB.z * q2 + kB.w * q3;
        pA += __shfl_xor_sync(0xffffffffu, pA, 1);
        pB += __shfl_xor_sync(0xffffffffu, pB, 1);
        pA += __shfl_xor_sync(0xffffffffu, pA, 2);
        pB += __shfl_xor_sync(0xffffffffu, pB, 2);

        float xA = __expf(pA + cst);
        float xB = __expf(pB + cst);
        ssum += xA + xB;
        if (WRITE_ALPHA && j == 0) {
            exbuf[(size_t)eidA * HEADS + h] = xA;
            exbuf[(size_t)eidB * HEADS + h] = xB;
        }
        av0 = fmaf(xA, vA.x, av0); av1 = fmaf(xA, vA.y, av1);
        av2 = fmaf(xA, vA.z, av2); av3 = fmaf(xA, vA.w, av3);
        av0 = fmaf(xB, vB.x, av0); av1 = fmaf(xB, vB.y, av1);
        av2 = fmaf(xB, vB.z, av2); av3 = fmaf(xB, vB.w, av3);
    }
    for (; i < cnt; i += 2) {
        int idx = i + half;
        bool act = idx < cnt;
        int2 es = bp[act ? idx : i];
        float4 kf = kv4[(size_t)es.y * 32 + kidx];
        float4 vf = kv4[(size_t)es.y * 32 + vidx];
        float p = kf.x * q0 + kf.y * q1 + kf.z * q2 + kf.w * q3;
        p += __shfl_xor_sync(0xffffffffu, p, 1);
        p += __shfl_xor_sync(0xffffffffu, p, 2);
        float ex = act ? __expf(p + cst) : 0.f;
        ssum += ex;
        if (WRITE_ALPHA && j == 0 && act) exbuf[(size_t)es.x * HEADS + h] = ex;
        av0 = fmaf(ex, vf.x, av0); av1 = fmaf(ex, vf.y, av1);
        av2 = fmaf(ex, vf.z, av2); av3 = fmaf(ex, vf.w, av3);
    }

    ssum += __shfl_xor_sync(0xffffffffu, ssum, 16);
    av0 += __shfl_xor_sync(0xffffffffu, av0, 16);
    av1 += __shfl_xor_sync(0xffffffffu, av1, 16);
    av2 += __shfl_xor_sync(0xffffffffu, av2, 16);
    av3 += __shfl_xor_sync(0xffffffffu, av3, 16);

    float r = 1.0f / (ssum + 1e-16f);
    if (WRITE_ALPHA && half == 0 && j == 0) g_r[node * HEADS + h] = r;

    if (half == 0) {
        const float4 eb = *(const float4*)(wbar + hb + 4 * j);
        const float4 sk = *(const float4*)(g_s + (size_t)node * HDIM + hb + 4 * j);
        float4 o;
        o.x = fmaf(fmaf(ssum, eb.x, av0), r, sk.x);
        o.y = fmaf(fmaf(ssum, eb.y, av1), r, sk.y);
        o.z = fmaf(fmaf(ssum, eb.z, av2), r, sk.z);
        o.w = fmaf(fmaf(ssum, eb.w, av3), r, sk.w);
        *(float4*)(out + (size_t)node * HDIM + hb + 4 * j) = o;
    }
}

// ---------------- K7b: generic attention (fallback when edge_attr != ones) ----------------
template <bool WRITE_ALPHA>
__global__ void __launch_bounds__(256, 4) attn_kernel(
    const float* __restrict__ ea, const float* __restrict__ We,
    float* __restrict__ out, float* __restrict__ exbuf, int n)
{
    if (g_flag) return;

    __shared__ float sWe[EDIM * HDIM];
    __shared__ float sAcc[8][HDIM];
    for (int i = threadIdx.x; i < EDIM * HDIM; i += 256) sWe[i] = We[i];
    __syncthreads();

    int wid = threadIdx.x >> 5, lane = threadIdx.x & 31;
    int node = blockIdx.x * 8 + wid;
    if (node >= n) return;

    int half = lane >> 4;
    int h = (lane & 15) >> 2;
    int j = lane & 3;
    int hb = h * DDIM;
    int kidx = lane & 15;
    int vidx = 16 + (lane & 15);

    float q0, q1, q2, q3, t0, t1, t2, t3;
    {
        const float4* Q = (const float4*)(g_q + (size_t)node * HDIM + hb);
        float4 qa = Q[0], qb = Q[1], qc = Q[2], qd = Q[3];
        float4 qf = (j == 0) ? qa : (j == 1) ? qb : (j == 2) ? qc : qd;
        q0 = qf.x; q1 = qf.y; q2 = qf.z; q3 = qf.w;
        float tv[4];
#pragma unroll
        for (int cc = 0; cc < 4; cc++) {
            const float4* wr = (const float4*)(sWe + (4 * j + cc) * HDIM + hb);
            float4 w0 = wr[0], w1 = wr[1], w2 = wr[2], w3 = wr[3];
            float s = 0.f;
            s = fmaf(qa.x, w0.x, s); s = fmaf(qa.y, w0.y, s); s = fmaf(qa.z, w0.z, s); s = fmaf(qa.w, w0.w, s);
            s = fmaf(qb.x, w1.x, s); s = fmaf(qb.y, w1.y, s); s = fmaf(qb.z, w1.z, s); s = fmaf(qb.w, w1.w, s);
            s = fmaf(qc.x, w2.x, s); s = fmaf(qc.y, w2.y, s); s = fmaf(qc.z, w2.z, s); s = fmaf(qc.w, w2.w, s);
            s = fmaf(qd.x, w3.x, s); s = fmaf(qd.y, w3.y, s); s = fmaf(qd.z, w3.z, s); s = fmaf(qd.w, w3.w, s);
            tv[cc] = s;
        }
        t0 = tv[0]; t1 = tv[1]; t2 = tv[2]; t3 = tv[3];
    }

    const int2* bp = g_bkt + (size_t)node * BUCKET;
    int cnt = g_cnt[node];

    float av0 = 0.f, av1 = 0.f, av2 = 0.f, av3 = 0.f;
    float ae0 = 0.f, ae1 = 0.f, ae2 = 0.f, ae3 = 0.f;
    float ssum = 0.f;
    const float4* kv4 = (const float4*)g_kv;
    const float4* ea4 = (const float4*)ea;

    int i = 0;
    for (; i + 2 <= cnt; i += 2) {
        int4 eP = *(const int4*)(bp + i);
        int eid = half ? eP.z : eP.x;  int src = half ? eP.w : eP.y;
        float4 kf = kv4[(size_t)src * 32 + kidx];
        float4 vf = kv4[(size_t)src * 32 + vidx];
        float4 af = ea4[(size_t)eid * 4 + j];
        float p = kf.x * q0 + kf.y * q1 + kf.z * q2 + kf.w * q3
                + af.x * t0 + af.y * t1 + af.z * t2 + af.w * t3;
        p += __shfl_xor_sync(0xffffffffu, p, 1);
        p += __shfl_xor_sync(0xffffffffu, p, 2);
        float ex = __expf(p);
        ssum += ex;
        if (WRITE_ALPHA && j == 0) exbuf[(size_t)eid * HEADS + h] = ex;
        av0 = fmaf(ex, vf.x, av0); av1 = fmaf(ex, vf.y, av1);
        av2 = fmaf(ex, vf.z, av2); av3 = fmaf(ex, vf.w, av3);
        ae0 = fmaf(ex, af.x, ae0); ae1 = fmaf(ex, af.y, ae1);
        ae2 = fmaf(ex, af.z, ae2); ae3 = fmaf(ex, af.w, ae3);
    }
    for (; i < cnt; i += 2) {
        int idx = i + half;
        bool act = idx < cnt;
        int2 es = bp[act ? idx : i];
        float4 kf = kv4[(size_t)es.y * 32 + kidx];
        float4 vf = kv4[(size_t)es.y * 32 + vidx];
        float4 af = ea4[(size_t)es.x * 4 + j];
        float p = kf.x * q0 + kf.y * q1 + kf.z * q2 + kf.w * q3
                + af.x * t0 + af.y * t1 + af.z * t2 + af.w * t3;
        p += __shfl_xor_sync(0xffffffffu, p, 1);
        p += __shfl_xor_sync(0xffffffffu, p, 2);
        float ex = act ? __expf(p) : 0.f;
        ssum += ex;
        if (WRITE_ALPHA && j == 0 && act) exbuf[(size_t)es.x * HEADS + h] = ex;
        av0 = fmaf(ex, vf.x, av0); av1 = fmaf(ex, vf.y, av1);
        av2 = fmaf(ex, vf.z, av2); av3 = fmaf(ex, vf.w, av3);
        ae0 = fmaf(ex, af.x, ae0); ae1 = fmaf(ex, af.y, ae1);
        ae2 = fmaf(ex, af.z, ae2); ae3 = fmaf(ex, af.w, ae3);
    }

    ssum += __shfl_xor_sync(0xffffffffu, ssum, 16);
    av0 += __shfl_xor_sync(0xffffffffu, av0, 16);
    av1 += __shfl_xor_sync(0xffffffffu, av1, 16);
    av2 += __shfl_xor_sync(0xffffffffu, av2, 16);
    av3 += __shfl_xor_sync(0xffffffffu, av3, 16);
    ae0 += __shfl_xor_sync(0xffffffffu, ae0, 16);
    ae1 += __shfl_xor_sync(0xffffffffu, ae1, 16);
    ae2 += __shfl_xor_sync(0xffffffffu, ae2, 16);
    ae3 += __shfl_xor_sync(0xffffffffu, ae3, 16);

    float r = 1.0f / (ssum + 1e-16f);
    if (WRITE_ALPHA && half == 0 && j == 0) g_r[node * HEADS + h] = r;

    if (half == 0) {
        float* p = &sAcc[wid][hb + 4 * j];
        p[0] = ae0; p[1] = ae1; p[2] = ae2; p[3] = ae3;
    }
    __syncwarp();

    if (half == 0) {
        float e0 = 0.f, e1 = 0.f, e2 = 0.f, e3 = 0.f;
        const float* aC = &sAcc[wid][hb];
#pragma unroll
        for (int c = 0; c < 16; c++) {
            float ac = aC[c];
            const float4 wv = *(const float4*)(sWe + c * HDIM + hb + 4 * j);
            e0 = fmaf(ac, wv.x, e0); e1 = fmaf(ac, wv.y, e1);
            e2 = fmaf(ac, wv.z, e2); e3 = fmaf(ac, wv.w, e3);
        }
        const float4 sk = *(const float4*)(g_s + (size_t)node * HDIM + hb + 4 * j);
        float4 o;
        o.x = fmaf(av0 + e0, r, sk.x);
        o.y = fmaf(av1 + e1, r, sk.y);
        o.z = fmaf(av2 + e2, r, sk.z);
        o.w = fmaf(av3 + e3, r, sk.w);
        *(float4*)(out + (size_t)node * HDIM + hb + 4 * j) = o;
    }
}

// ---------------- K8: fused finish = edge_index float copy + alpha rescale ----------------
__global__ void __launch_bounds__(256) finish_kernel(
    const int* __restrict__ ei, float* __restrict__ out_ei,
    float* __restrict__ alpha, int E)
{
    int e = blockIdx.x * blockDim.x + threadIdx.x;
    if (e < E) {
        int s = ei[e];
        int d = ei[E + e];
        out_ei[e]     = (float)s;
        out_ei[E + e] = (float)d;
        float4 r = *(const float4*)(g_r + (size_t)d * HEADS);
        float4 a = *(const float4*)(alpha + (size_t)e * HEADS);
        a.x *= r.x; a.y *= r.y; a.z *= r.z; a.w *= r.w;
        *(float4*)(alpha + (size_t)e * HEADS) = a;
    }
}

// ---------------- host launcher ----------------
extern "C" void kernel_launch(void* const* d_in, const int* in_sizes, int n_in,
                              void* d_out, int out_size) {
    const float* x     = (const float*)d_in[0];
    const int*   ei    = (const int*)  d_in[1];
    const float* ea    = (const float*)d_in[2];
    const float* Wq    = (const float*)d_in[3];
    const float* bq    = (const float*)d_in[4];
    const float* Wk    = (const float*)d_in[5];
    const float* bk    = (const float*)d_in[6];
    const float* Wv    = (const float*)d_in[7];
    const float* bv    = (const float*)d_in[8];
    const float* We    = (const float*)d_in[9];
    const float* Wskip = (const float*)d_in[10];
    const float* bskip = (const float*)d_in[11];

    int n = in_sizes[0] / INF_DIM;
    int E = in_sizes[1] / 2;
    float* out = (float*)d_out;

    long long NHD = (long long)n * HDIM;
    int full = (out_size >= (int)(NHD + 2LL * E + (long long)E * HEADS)) ? 1 : 0;
    float* alpha_out = out + NHD + 2LL * E;

    static int smem_set = 0;
    const int SMEM_MMA = 65536 * 2 + 32768 + 1024;   // 164864
    if (!smem_set) {
        cudaFuncSetAttribute(mma_kernel, cudaFuncAttributeMaxDynamicSharedMemorySize, SMEM_MMA);
        smem_set = 1;
    }

    int total4 = n * 32;                 // n*128/4 float4s
    int Gx = (total4 + 255) / 256;       // split_x blocks
    int Gs = (E + 255) / 256;            // scatter blocks

    zero_all_kernel<<<(n + 255) / 256, 256>>>(We, n);                            // 1
    split_w_kernel<<<128, 256>>>(Wq, Wk, Wv, Wskip);                             // 2
    splitx_scatter_kernel<<<Gx + Gs, 256>>>(x, ei, ea, total4, E, Gx);           // 3
    mma_kernel<<<(n + 31) / 32, 256, SMEM_MMA>>>(bq, bk, bv, bskip, n);          // 4 -> ncu
    check_kernel<<<1, 128>>>(x, Wq, bq, Wk, bk, Wv, bv, Wskip, bskip, n);        // 5
    fallback_gemm_kernel<<<(n + 7) / 8, 128>>>(x, Wq, bq, Wk, bk, Wv, bv,        // 6
                                               Wskip, bskip, n);
    if (full) {
        attn_ones_kernel<true><<<(n + 7) / 8, 256>>>(out, alpha_out, n);         // 7
        attn_kernel<true><<<(n + 7) / 8, 256>>>(ea, We, out, alpha_out, n);      // 8
        finish_kernel<<<(E + 255) / 256, 256>>>(ei, out + NHD, alpha_out, E);    // 9
    } else {
        attn_ones_kernel<false><<<(n + 7) / 8, 256>>>(out, nullptr, n);
        attn_kernel<false><<<(n + 7) / 8, 256>>>(ea, We, out, nullptr, n);
    }
}